// round 15
// baseline (speedup 1.0000x reference)
#include <cuda_runtime.h>
#include <stdint.h>
#include <math.h>

#define NB   64
#define TT   2048
#define DH   256
#define MTOT (NB * TT)

// ---------------------------------------------------------------------------
// XLA EmitFastTanh, with_fma=true (VERIFIED bit-exact): fused Horner,
// clamp +-7.99881172180175781, |x| < 0.0004 -> x, IEEE RN divide.
// ---------------------------------------------------------------------------
__device__ __forceinline__ float tanh_xla(float x) {
    float a  = fabsf(x);
    float xc = fminf(fmaxf(x, -7.99881172180175781f), 7.99881172180175781f);
    float x2 = xc * xc;
    float p = __fmaf_rn(x2, -2.76076847742355e-16f, 2.00018790482477e-13f);
    p = __fmaf_rn(x2, p, -8.60467152213735e-11f);
    p = __fmaf_rn(x2, p,  5.12229709037114e-08f);
    p = __fmaf_rn(x2, p,  1.48572235717979e-05f);
    p = __fmaf_rn(x2, p,  6.37261928875436e-04f);
    p = __fmaf_rn(x2, p,  4.89352455891786e-03f);
    p = xc * p;
    float q = __fmaf_rn(x2, 1.19825839466702e-06f, 1.18534705686654e-04f);
    q = __fmaf_rn(x2, q, 2.26843463243900e-03f);
    q = __fmaf_rn(x2, q, 4.89352518554385e-03f);
    float r = __fdiv_rn(p, q);
    return (a < 0.0004f) ? x : r;
}

// ===========================================================================
// Kernel A: out = X @ Wx + bx  (131072 x 256 x 256), bit-exact FFMA chain.
// Double-buffered smem (unchanged — adequate).
// ===========================================================================
__global__ void __launch_bounds__(256)
xproj_kernel(const float* __restrict__ X, const float* __restrict__ W,
             const float* __restrict__ bx, float* __restrict__ out)
{
    __shared__ float As[2][8][128];
    __shared__ float Bs[2][8][128];

    const int tid = threadIdx.x;
    const int bm = blockIdx.x * 128;
    const int bn = blockIdx.y * 128;
    const int tx = tid & 15, ty = tid >> 4;
    const int m0 = ty * 8, n0 = tx * 8;
    const int arow = tid >> 1, acol4 = (tid & 1) * 4;
    const int brow = tid >> 5, bcol4 = (tid & 31) * 4;

    float acc[8][8];
    #pragma unroll
    for (int i = 0; i < 8; i++)
        #pragma unroll
        for (int j = 0; j < 8; j++) acc[i][j] = 0.f;

    float4 av = *(const float4*)&X[(size_t)(bm + arow) * DH + acol4];
    float4 bv = *(const float4*)&W[(size_t)brow * DH + bn + bcol4];
    As[0][acol4 + 0][arow] = av.x; As[0][acol4 + 1][arow] = av.y;
    As[0][acol4 + 2][arow] = av.z; As[0][acol4 + 3][arow] = av.w;
    *(float4*)&Bs[0][brow][bcol4] = bv;
    __syncthreads();

    #pragma unroll 4
    for (int it = 0; it < 32; it++) {
        const int cur = it & 1;
        if (it < 31) {
            const int k0 = (it + 1) * 8;
            av = *(const float4*)&X[(size_t)(bm + arow) * DH + k0 + acol4];
            bv = *(const float4*)&W[(size_t)(k0 + brow) * DH + bn + bcol4];
        }
        #pragma unroll
        for (int k = 0; k < 8; k++) {
            float a[8], b[8];
            *(float4*)(a)     = *(const float4*)&As[cur][k][m0];
            *(float4*)(a + 4) = *(const float4*)&As[cur][k][m0 + 4];
            *(float4*)(b)     = *(const float4*)&Bs[cur][k][n0];
            *(float4*)(b + 4) = *(const float4*)&Bs[cur][k][n0 + 4];
            #pragma unroll
            for (int i = 0; i < 8; i++)
                #pragma unroll
                for (int j = 0; j < 8; j++)
                    acc[i][j] = __fmaf_rn(a[i], b[j], acc[i][j]);
        }
        if (it < 31) {
            const int nxt = cur ^ 1;
            As[nxt][acol4 + 0][arow] = av.x; As[nxt][acol4 + 1][arow] = av.y;
            As[nxt][acol4 + 2][arow] = av.z; As[nxt][acol4 + 3][arow] = av.w;
            *(float4*)&Bs[nxt][brow][bcol4] = bv;
            __syncthreads();
        }
    }

    float bxr[8];
    #pragma unroll
    for (int j = 0; j < 8; j++) bxr[j] = bx[bn + n0 + j];
    #pragma unroll
    for (int i = 0; i < 8; i++) {
        const size_t row = (size_t)(bm + m0 + i);
        #pragma unroll
        for (int j = 0; j < 8; j += 4) {
            float4 v;
            v.x = __fadd_rn(acc[i][j+0], bxr[j+0]);
            v.y = __fadd_rn(acc[i][j+1], bxr[j+1]);
            v.z = __fadd_rn(acc[i][j+2], bxr[j+2]);
            v.w = __fadd_rn(acc[i][j+3], bxr[j+3]);
            *(float4*)&out[row * DH + bn + n0 + j] = v;
        }
    }
}

// ===========================================================================
// Kernel B: recurrence. One CTA/batch, 256 thr = 1/col. Bit-exact chain:
// k ascending 0..255, (xp+acc)+bh, tanh_xla.
// k = 0..95   : Wh from smem (transposed wT[c][k], stride 100 -> LDS.128
//               conflict-free), depth-3 pipelined; first 3 chunks restocked
//               during the PREVIOUS step's register section (w is t-invariant)
// k = 96..255 : Wh in registers (160/thread)
// h broadcast LDS.128, depth-3 pipelined throughout.
// ===========================================================================
#define NSMEM_K    96
#define WT_STRIDE  100
#define REC_SMEM_BYTES ((256 * WT_STRIDE + 2 * DH) * 4)

__global__ void __launch_bounds__(256, 1)
rnn_rec_kernel(const float* __restrict__ Wh, const float* __restrict__ bh,
               const float* __restrict__ h_init, float* __restrict__ out)
{
    extern __shared__ float sm[];
    float* wT = sm;                       // [256][WT_STRIDE]: Wh rows 0..95
    float* hA = sm + 256 * WT_STRIDE;     // [256]
    float* hB = hA + DH;                  // [256]

    const int b = blockIdx.x;
    const int c = threadIdx.x;

    // Wh rows 0..95 -> transposed smem wT[c][0..95]
    #pragma unroll
    for (int k = 0; k < NSMEM_K; k++)
        wT[c * WT_STRIDE + k] = Wh[(size_t)k * DH + c];

    // Wh rows 96..255, column c -> registers (coalesced LDG per k)
    float wreg[160];
    #pragma unroll
    for (int k = 0; k < 160; k++)
        wreg[k] = Wh[(size_t)(NSMEM_K + k) * DH + c];

    hA[c] = h_init[(size_t)b * DH + c];
    const float bias = bh[c];
    __syncthreads();

    float* hcur = hA;
    float* hnxt = hB;
    float* obase = out + (size_t)b * TT * DH + c;
    const float4* wt4 = (const float4*)(wT + c * WT_STRIDE);   // 24 float4

    // persistent w staging: chunks 0,1,2 (restocked at end of each step)
    float4 ws0a = wt4[0], ws0b = wt4[1];
    float4 ws1a = wt4[2], ws1b = wt4[3];
    float4 ws2a = wt4[4], ws2b = wt4[5];

    for (int t = 0; t < TT; t++) {
        float xp = obase[(size_t)t * DH];          // hidden under the chain

        const float4* h4 = (const float4*)hcur;

        // h staging: chunks 0,1,2 (cold ~45 cyc after barrier; unavoidable)
        float4 hs0a = h4[0], hs0b = h4[1];
        float4 hs1a = h4[2], hs1b = h4[3];
        float4 hs2a = h4[4], hs2b = h4[5];

        float acc = 0.f;

        // ---- part 1: chunks 0..11 (k = 0..95), w from smem, depth-3 ----
        #pragma unroll
        for (int ch = 0; ch < 12; ch++) {
            float4 hna, hnb, wna, wnb;
            hna = h4[2 * ch + 6]; hnb = h4[2 * ch + 7];     // chunk ch+3 (<=14)
            if (ch <= 8) { wna = wt4[2 * ch + 6]; wnb = wt4[2 * ch + 7]; }

            acc = __fmaf_rn(hs0a.x, ws0a.x, acc);
            acc = __fmaf_rn(hs0a.y, ws0a.y, acc);
            acc = __fmaf_rn(hs0a.z, ws0a.z, acc);
            acc = __fmaf_rn(hs0a.w, ws0a.w, acc);
            acc = __fmaf_rn(hs0b.x, ws0b.x, acc);
            acc = __fmaf_rn(hs0b.y, ws0b.y, acc);
            acc = __fmaf_rn(hs0b.z, ws0b.z, acc);
            acc = __fmaf_rn(hs0b.w, ws0b.w, acc);

            hs0a = hs1a; hs0b = hs1b; hs1a = hs2a; hs1b = hs2b;
            hs2a = hna;  hs2b = hnb;
            ws0a = ws1a; ws0b = ws1b; ws1a = ws2a; ws1b = ws2b;
            ws2a = wna;  ws2b = wnb;
        }

        // ---- part 2: chunks 12..31 (k = 96..255), w in registers ----
        #pragma unroll
        for (int ch = 12; ch < 32; ch++) {
            float4 hna, hnb;
            if (ch <= 28) { hna = h4[2 * ch + 6]; hnb = h4[2 * ch + 7]; }

            // restock next step's w chunks 0..2 (t-invariant, big lead)
            if (ch == 26) { ws0a = wt4[0]; ws0b = wt4[1]; }
            if (ch == 27) { ws1a = wt4[2]; ws1b = wt4[3]; }
            if (ch == 28) { ws2a = wt4[4]; ws2b = wt4[5]; }

            const int kb = (ch - 12) * 8;
            acc = __fmaf_rn(hs0a.x, wreg[kb + 0], acc);
            acc = __fmaf_rn(hs0a.y, wreg[kb + 1], acc);
            acc = __fmaf_rn(hs0a.z, wreg[kb + 2], acc);
            acc = __fmaf_rn(hs0a.w, wreg[kb + 3], acc);
            acc = __fmaf_rn(hs0b.x, wreg[kb + 4], acc);
            acc = __fmaf_rn(hs0b.y, wreg[kb + 5], acc);
            acc = __fmaf_rn(hs0b.z, wreg[kb + 6], acc);
            acc = __fmaf_rn(hs0b.w, wreg[kb + 7], acc);

            hs0a = hs1a; hs0b = hs1b; hs1a = hs2a; hs1b = hs2b;
            hs2a = hna;  hs2b = hnb;
        }

        float pre = __fadd_rn(__fadd_rn(xp, acc), bias);
        float h = tanh_xla(pre);

        hnxt[c] = h;
        obase[(size_t)t * DH] = h;

        __syncthreads();

        float* tmp = hcur; hcur = hnxt; hnxt = tmp;
    }
}

// ===========================================================================
extern "C" void kernel_launch(void* const* d_in, const int* in_sizes, int n_in,
                              void* d_out, int out_size)
{
    const float* seq_x  = (const float*)d_in[0];
    const float* Wx     = (const float*)d_in[1];
    const float* bx     = (const float*)d_in[2];
    const float* Wh     = (const float*)d_in[3];
    const float* bh     = (const float*)d_in[4];
    const float* h_init = (const float*)d_in[5];
    float* out = (float*)d_out;

    xproj_kernel<<<dim3(MTOT / 128, DH / 128), 256>>>(seq_x, Wx, bx, out);

    cudaFuncSetAttribute(rnn_rec_kernel,
                         cudaFuncAttributeMaxDynamicSharedMemorySize,
                         REC_SMEM_BYTES);
    rnn_rec_kernel<<<NB, 256, REC_SMEM_BYTES>>>(Wh, bh, h_init, out);
}

// round 16
// speedup vs baseline: 1.0562x; 1.0562x over previous
#include <cuda_runtime.h>
#include <stdint.h>
#include <math.h>

#define NB   64
#define TT   2048
#define DH   256
#define MTOT (NB * TT)

// ---------------------------------------------------------------------------
// XLA EmitFastTanh, with_fma=true (VERIFIED bit-exact): fused Horner,
// clamp +-7.99881172180175781, |x| < 0.0004 -> x, IEEE RN divide.
// ---------------------------------------------------------------------------
__device__ __forceinline__ float tanh_xla(float x) {
    float a  = fabsf(x);
    float xc = fminf(fmaxf(x, -7.99881172180175781f), 7.99881172180175781f);
    float x2 = xc * xc;
    float p = __fmaf_rn(x2, -2.76076847742355e-16f, 2.00018790482477e-13f);
    p = __fmaf_rn(x2, p, -8.60467152213735e-11f);
    p = __fmaf_rn(x2, p,  5.12229709037114e-08f);
    p = __fmaf_rn(x2, p,  1.48572235717979e-05f);
    p = __fmaf_rn(x2, p,  6.37261928875436e-04f);
    p = __fmaf_rn(x2, p,  4.89352455891786e-03f);
    p = xc * p;
    float q = __fmaf_rn(x2, 1.19825839466702e-06f, 1.18534705686654e-04f);
    q = __fmaf_rn(x2, q, 2.26843463243900e-03f);
    q = __fmaf_rn(x2, q, 4.89352518554385e-03f);
    float r = __fdiv_rn(p, q);
    return (a < 0.0004f) ? x : r;
}

// ===========================================================================
// Kernel A: out = X @ Wx + bx  (131072 x 256 x 256), bit-exact FFMA chain.
// Double-buffered smem (proven, unchanged).
// ===========================================================================
__global__ void __launch_bounds__(256)
xproj_kernel(const float* __restrict__ X, const float* __restrict__ W,
             const float* __restrict__ bx, float* __restrict__ out)
{
    __shared__ float As[2][8][128];
    __shared__ float Bs[2][8][128];

    const int tid = threadIdx.x;
    const int bm = blockIdx.x * 128;
    const int bn = blockIdx.y * 128;
    const int tx = tid & 15, ty = tid >> 4;
    const int m0 = ty * 8, n0 = tx * 8;
    const int arow = tid >> 1, acol4 = (tid & 1) * 4;
    const int brow = tid >> 5, bcol4 = (tid & 31) * 4;

    float acc[8][8];
    #pragma unroll
    for (int i = 0; i < 8; i++)
        #pragma unroll
        for (int j = 0; j < 8; j++) acc[i][j] = 0.f;

    float4 av = *(const float4*)&X[(size_t)(bm + arow) * DH + acol4];
    float4 bv = *(const float4*)&W[(size_t)brow * DH + bn + bcol4];
    As[0][acol4 + 0][arow] = av.x; As[0][acol4 + 1][arow] = av.y;
    As[0][acol4 + 2][arow] = av.z; As[0][acol4 + 3][arow] = av.w;
    *(float4*)&Bs[0][brow][bcol4] = bv;
    __syncthreads();

    #pragma unroll 4
    for (int it = 0; it < 32; it++) {
        const int cur = it & 1;
        if (it < 31) {
            const int k0 = (it + 1) * 8;
            av = *(const float4*)&X[(size_t)(bm + arow) * DH + k0 + acol4];
            bv = *(const float4*)&W[(size_t)(k0 + brow) * DH + bn + bcol4];
        }
        #pragma unroll
        for (int k = 0; k < 8; k++) {
            float a[8], b[8];
            *(float4*)(a)     = *(const float4*)&As[cur][k][m0];
            *(float4*)(a + 4) = *(const float4*)&As[cur][k][m0 + 4];
            *(float4*)(b)     = *(const float4*)&Bs[cur][k][n0];
            *(float4*)(b + 4) = *(const float4*)&Bs[cur][k][n0 + 4];
            #pragma unroll
            for (int i = 0; i < 8; i++)
                #pragma unroll
                for (int j = 0; j < 8; j++)
                    acc[i][j] = __fmaf_rn(a[i], b[j], acc[i][j]);
        }
        if (it < 31) {
            const int nxt = cur ^ 1;
            As[nxt][acol4 + 0][arow] = av.x; As[nxt][acol4 + 1][arow] = av.y;
            As[nxt][acol4 + 2][arow] = av.z; As[nxt][acol4 + 3][arow] = av.w;
            *(float4*)&Bs[nxt][brow][bcol4] = bv;
            __syncthreads();
        }
    }

    float bxr[8];
    #pragma unroll
    for (int j = 0; j < 8; j++) bxr[j] = bx[bn + n0 + j];
    #pragma unroll
    for (int i = 0; i < 8; i++) {
        const size_t row = (size_t)(bm + m0 + i);
        #pragma unroll
        for (int j = 0; j < 8; j += 4) {
            float4 v;
            v.x = __fadd_rn(acc[i][j+0], bxr[j+0]);
            v.y = __fadd_rn(acc[i][j+1], bxr[j+1]);
            v.z = __fadd_rn(acc[i][j+2], bxr[j+2]);
            v.w = __fadd_rn(acc[i][j+3], bxr[j+3]);
            *(float4*)&out[row * DH + bn + n0 + j] = v;
        }
    }
}

// ===========================================================================
// Kernel B: recurrence. One CTA/batch, 256 thr = 1/col. Bit-exact chain:
// k ascending 0..255, (xp+acc)+bh, tanh_xla.
// Wh source INTERLEAVED by chunk (8 k's): chunks with ch%8 in {1,3,6} come
// from smem (12 chunks = 96 k, transposed wT[c][k], stride 100 -> LDS.128
// conflict-free), the other 20 chunks (160 k) from registers. Even spreading
// keeps crossbar demand uniform (~320 wf per 256-cyc group) instead of the
// R13/R14 end-of-step burst. Chain arithmetic order is UNCHANGED.
// ===========================================================================
#define WT_STRIDE  100
#define REC_SMEM_BYTES ((256 * WT_STRIDE + 2 * DH) * 4)

__global__ void __launch_bounds__(256, 1)
rnn_rec_kernel(const float* __restrict__ Wh, const float* __restrict__ bh,
               const float* __restrict__ h_init, float* __restrict__ out)
{
    // chunk ch sources w from smem iff ch%8 in {1,3,6}
    constexpr bool IS_SMEM[32] = {
        false,true,false,true,false,false,true,false,
        false,true,false,true,false,false,true,false,
        false,true,false,true,false,false,true,false,
        false,true,false,true,false,false,true,false};
    constexpr int REG_ORD[32] = {
        0,0,1,0,2,3,0,4, 5,0,6,0,7,8,0,9,
        10,0,11,0,12,13,0,14, 15,0,16,0,17,18,0,19};
    constexpr int SMEM_ORD[32] = {
        0,0,0,1,0,0,2,0, 0,3,0,4,0,0,5,0,
        0,6,0,7,0,0,8,0, 0,9,0,10,0,0,11,0};

    extern __shared__ float sm[];
    float* wT = sm;                       // [256][WT_STRIDE]: 12 smem chunks
    float* hA = sm + 256 * WT_STRIDE;     // [256]
    float* hB = hA + DH;                  // [256]

    const int b = blockIdx.x;
    const int c = threadIdx.x;

    // distribute Wh rows: smem chunks -> wT[c][slot*8 + i], reg chunks -> wreg
    float wreg[160];
    #pragma unroll
    for (int ch = 0; ch < 32; ch++) {
        #pragma unroll
        for (int i = 0; i < 8; i++) {
            float v = Wh[(size_t)(ch * 8 + i) * DH + c];
            if (IS_SMEM[ch]) wT[c * WT_STRIDE + SMEM_ORD[ch] * 8 + i] = v;
            else             wreg[REG_ORD[ch] * 8 + i] = v;
        }
    }

    hA[c] = h_init[(size_t)b * DH + c];
    const float bias = bh[c];
    __syncthreads();

    float* hcur = hA;
    float* hnxt = hB;
    float* obase = out + (size_t)b * TT * DH + c;
    const float4* wt4 = (const float4*)(wT + c * WT_STRIDE);   // 24 float4

    for (int t = 0; t < TT; t++) {
        float xp = obase[(size_t)t * DH];          // hidden under the chain

        const float4* h4 = (const float4*)hcur;

        // h staging depth-2; w smem staging: 2 pending chunks
        float4 h0 = h4[0], h1 = h4[1], h2 = h4[2], h3 = h4[3];
        float4 w0a = wt4[0], w0b = wt4[1];         // smem chunk slot 0
        float4 w1a = wt4[2], w1b = wt4[3];         // smem chunk slot 1

        float acc = 0.f;

        #pragma unroll
        for (int ch = 0; ch < 32; ch++) {
            float4 hn0, hn1;
            if (ch < 30) { hn0 = h4[2 * ch + 4]; hn1 = h4[2 * ch + 5]; }

            if (IS_SMEM[ch]) {
                // prefetch smem chunk slot+2 (arrives ~5 chunks later)
                float4 wn0, wn1;
                if (SMEM_ORD[ch] + 2 < 12) {
                    wn0 = wt4[(SMEM_ORD[ch] + 2) * 2];
                    wn1 = wt4[(SMEM_ORD[ch] + 2) * 2 + 1];
                }
                acc = __fmaf_rn(h0.x, w0a.x, acc);
                acc = __fmaf_rn(h0.y, w0a.y, acc);
                acc = __fmaf_rn(h0.z, w0a.z, acc);
                acc = __fmaf_rn(h0.w, w0a.w, acc);
                acc = __fmaf_rn(h1.x, w0b.x, acc);
                acc = __fmaf_rn(h1.y, w0b.y, acc);
                acc = __fmaf_rn(h1.z, w0b.z, acc);
                acc = __fmaf_rn(h1.w, w0b.w, acc);
                w0a = w1a; w0b = w1b; w1a = wn0; w1b = wn1;
            } else {
                const int kb = REG_ORD[ch] * 8;
                acc = __fmaf_rn(h0.x, wreg[kb + 0], acc);
                acc = __fmaf_rn(h0.y, wreg[kb + 1], acc);
                acc = __fmaf_rn(h0.z, wreg[kb + 2], acc);
                acc = __fmaf_rn(h0.w, wreg[kb + 3], acc);
                acc = __fmaf_rn(h1.x, wreg[kb + 4], acc);
                acc = __fmaf_rn(h1.y, wreg[kb + 5], acc);
                acc = __fmaf_rn(h1.z, wreg[kb + 6], acc);
                acc = __fmaf_rn(h1.w, wreg[kb + 7], acc);
            }

            h0 = h2; h1 = h3; h2 = hn0; h3 = hn1;
        }

        float pre = __fadd_rn(__fadd_rn(xp, acc), bias);
        float h = tanh_xla(pre);

        hnxt[c] = h;
        obase[(size_t)t * DH] = h;

        __syncthreads();

        float* tmp = hcur; hcur = hnxt; hnxt = tmp;
    }
}

// ===========================================================================
extern "C" void kernel_launch(void* const* d_in, const int* in_sizes, int n_in,
                              void* d_out, int out_size)
{
    const float* seq_x  = (const float*)d_in[0];
    const float* Wx     = (const float*)d_in[1];
    const float* bx     = (const float*)d_in[2];
    const float* Wh     = (const float*)d_in[3];
    const float* bh     = (const float*)d_in[4];
    const float* h_init = (const float*)d_in[5];
    float* out = (float*)d_out;

    xproj_kernel<<<dim3(MTOT / 128, DH / 128), 256>>>(seq_x, Wx, bx, out);

    cudaFuncSetAttribute(rnn_rec_kernel,
                         cudaFuncAttributeMaxDynamicSharedMemorySize,
                         REC_SMEM_BYTES);
    rnn_rec_kernel<<<NB, 256, REC_SMEM_BYTES>>>(Wh, bh, h_init, out);
}